// round 4
// baseline (speedup 1.0000x reference)
#include <cuda_runtime.h>
#include <cuda_bf16.h>
#include <cstdint>

#define DF   64
#define DC   256
#define HF   240
#define WF   320
#define HW   (HF*WF)
#define LC   4800
#define WW   25
#define NMAX 16384
#define BST  72        // bf16 row stride for ldmatrix tiles (144B, conflict-free)

typedef unsigned long long u64;
typedef unsigned int u32;
typedef unsigned short u16;

__device__ float g_Wfused[DC * DF];
__device__ float g_biasf[DF];
__device__ float g_cc[2 * NMAX * DF];
__device__ u16   g_Bhi[DF * BST];
__device__ u16   g_Blo[DF * BST];

// ================= helpers =================
__device__ __forceinline__ u64 ffma2(u64 a, u64 b, u64 c) {
    u64 d; asm("fma.rn.f32x2 %0, %1, %2, %3;" : "=l"(d) : "l"(a), "l"(b), "l"(c)); return d;
}
__device__ __forceinline__ u64 dup2(float x) {
    u64 d; asm("mov.b64 %0, {%1, %1};" : "=l"(d) : "f"(x)); return d;
}
__device__ __forceinline__ float2 up2(u64 v) {
    float2 r; asm("mov.b64 {%0, %1}, %2;" : "=f"(r.x), "=f"(r.y) : "l"(v)); return r;
}
__device__ __forceinline__ u32 smem_u32(const void* p) {
    u32 a; asm("{ .reg .u64 t; cvta.to.shared.u64 t, %1; cvt.u32.u64 %0, t; }" : "=r"(a) : "l"(p));
    return a;
}
__device__ __forceinline__ void ldsm_x4(u32* r, u32 addr) {
    asm volatile("ldmatrix.sync.aligned.m8n8.x4.shared.b16 {%0,%1,%2,%3}, [%4];"
                 : "=r"(r[0]), "=r"(r[1]), "=r"(r[2]), "=r"(r[3]) : "r"(addr));
}
__device__ __forceinline__ void ldsm_x2(u32* r, u32 addr) {
    asm volatile("ldmatrix.sync.aligned.m8n8.x2.shared.b16 {%0,%1}, [%2];"
                 : "=r"(r[0]), "=r"(r[1]) : "r"(addr));
}
__device__ __forceinline__ void mma_bf16(float* d, const u32* a, const u32* b) {
    asm volatile("mma.sync.aligned.m16n8k16.row.col.f32.bf16.bf16.f32 "
                 "{%0,%1,%2,%3}, {%4,%5,%6,%7}, {%8,%9}, {%0,%1,%2,%3};"
                 : "+f"(d[0]), "+f"(d[1]), "+f"(d[2]), "+f"(d[3])
                 : "r"(a[0]), "r"(a[1]), "r"(a[2]), "r"(a[3]), "r"(b[0]), "r"(b[1]));
}

// ================= weight fusion =================
__global__ void fuse_weights_kernel(const float* __restrict__ Wd,
                                    const float* __restrict__ Wm,
                                    const float* __restrict__ bd,
                                    const float* __restrict__ bm) {
    int i = blockIdx.x, j = threadIdx.x;
    float acc = 0.f;
#pragma unroll
    for (int k = 0; k < DF; k++)
        acc += Wd[i * DF + k] * Wm[(DF + k) * DF + j];
    g_Wfused[i * DF + j] = acc;
    if (i == 0) {
        float b = bm[j];
#pragma unroll
        for (int k = 0; k < DF; k++)
            b += bd[k] * Wm[(DF + k) * DF + j];
        g_biasf[j] = b;
    }
}

// B[n][k] = Wm_top[k][n], split to bf16 hi/lo, padded stride
__global__ void prep_B_kernel(const float* __restrict__ Wm) {
    int n = blockIdx.x, k = threadIdx.x;
    float v = Wm[k * DF + n];
    __nv_bfloat16 h = __float2bfloat16(v);
    float lo = v - __bfloat162float(h);
    __nv_bfloat16 l = __float2bfloat16(lo);
    g_Bhi[n * BST + k] = *(u16*)&h;
    g_Blo[n * BST + k] = *(u16*)&l;
}

// ================= coarse projection (fp32 exact) =================
#define CB_ITEMS 32
#define CV_STR   258

__global__ __launch_bounds__(128) void coarse_kernel(
    const float* __restrict__ c0, const float* __restrict__ c1,
    const int* __restrict__ b_ids, const int* __restrict__ ci, int N)
{
    __shared__ float s_cv[CB_ITEMS * CV_STR];
    __shared__ int   s_off[CB_ITEMS];
    __shared__ int   s_s[CB_ITEMS];

    int tid = threadIdx.x;
    int base = blockIdx.x * CB_ITEMS;
    int total = 2 * N;

    if (tid < CB_ITEMS) {
        int item = base + tid;
        int s = 0, off = 0;
        if (item < total) {
            s = item >= N;
            int p = item - s * N;
            off = (__ldg(b_ids + p) * LC + __ldg(ci + p)) * DC;
        }
        s_s[tid] = s; s_off[tid] = off;
    }
    __syncthreads();

    for (int idx = tid; idx < CB_ITEMS * DC; idx += 128) {
        int it = idx >> 8, k = idx & 255;
        const float* src = s_s[it] ? c1 : c0;
        s_cv[it * CV_STR + k] = __ldg(src + s_off[it] + k);
    }
    __syncthreads();

    int ig = tid >> 4, cgp = tid & 15;
    u64 acc[4][2];
#pragma unroll
    for (int m = 0; m < 4; m++) { acc[m][0] = 0ull; acc[m][1] = 0ull; }
    const float* cv0 = s_cv + (4 * ig) * CV_STR;

#pragma unroll 4
    for (int k = 0; k < DC; k++) {
        const u64* wq = (const u64*)(g_Wfused + k * DF + cgp * 4);
        u64 w0 = wq[0], w1 = wq[1];
#pragma unroll
        for (int m = 0; m < 4; m++) {
            u64 a = dup2(cv0[m * CV_STR + k]);
            acc[m][0] = ffma2(a, w0, acc[m][0]);
            acc[m][1] = ffma2(a, w1, acc[m][1]);
        }
    }
    float b0 = g_biasf[cgp * 4], b1 = g_biasf[cgp * 4 + 1];
    float b2 = g_biasf[cgp * 4 + 2], b3 = g_biasf[cgp * 4 + 3];
#pragma unroll
    for (int m = 0; m < 4; m++) {
        int item = base + 4 * ig + m;
        if (item < total) {
            float2 x0 = up2(acc[m][0]), x1 = up2(acc[m][1]);
            *(float4*)(g_cc + (size_t)item * DF + cgp * 4) =
                make_float4(x0.x + b0, x0.y + b1, x1.x + b2, x1.y + b3);
        }
    }
}

// ================= main kernel: mma.sync bf16 3x-split =================
// dynamic smem layout (bytes):
#define SO_BHI 0
#define SO_BLO (SO_BHI + DF * BST * 2)          // 9216
#define SO_A   (SO_BLO + DF * BST * 2)          // 18432
#define A_ITEM (2 * 32 * BST * 2)               // hi+lo per item = 9216
#define SMEM_TOTAL (SO_A + 4 * A_ITEM)          // 55296

__global__ __launch_bounds__(128) void fine_main_kernel(
    const float* __restrict__ f0, const float* __restrict__ f1,
    const int* __restrict__ b_ids, const int* __restrict__ cy,
    const int* __restrict__ cx,
    float* __restrict__ out, int N)
{
    extern __shared__ char smem[];
    const u32 sb = smem_u32(smem);
    const int tid = threadIdx.x;
    const int wid = tid >> 5;
    const int lane = tid & 31;
    const int total = 2 * N;

    // ---- copy B hi/lo (18 KB, linear) ----
    {
        const float4* s0 = (const float4*)g_Bhi;   // hi then lo are adjacent? no: copy separately
        float4* d0 = (float4*)(smem + SO_BHI);
        for (int i = tid; i < (DF * BST * 2) / 16; i += 128) d0[i] = s0[i];
        const float4* s1 = (const float4*)g_Blo;
        float4* d1 = (float4*)(smem + SO_BLO);
        for (int i = tid; i < (DF * BST * 2) / 16; i += 128) d1[i] = s1[i];
    }

    // ---- per-warp gather of this item's window, bf16 hi/lo split ----
    int item = blockIdx.x * 4 + wid;
    int itemc = item < total ? item : total - 1;
    {
        int s = itemc >= N;
        int p = itemc - s * N;
        const float* fsrc = s ? f1 : f0;
        int b = __ldg(b_ids + p), y = __ldg(cy + p), x = __ldg(cx + p);
        const float* fbase = fsrc + (size_t)b * (DF * HW) + (size_t)(y - 2) * WF + (x - 2);

        u16* ahi = (u16*)(smem + SO_A + wid * A_ITEM);
        u16* alo = ahi + 32 * BST;
        for (int idx = lane; idx < WW * DF; idx += 32) {
            int ch  = idx / WW;
            int pos = idx - ch * WW;
            int dy  = pos / 5;
            int dx  = pos - dy * 5;
            float v = __ldg(fbase + ch * HW + dy * WF + dx);
            __nv_bfloat16 h = __float2bfloat16(v);
            float lo = v - __bfloat162float(h);
            __nv_bfloat16 l = __float2bfloat16(lo);
            ahi[pos * BST + ch] = *(u16*)&h;
            alo[pos * BST + ch] = *(u16*)&l;
        }
    }
    __syncthreads();

    // ---- ldmatrix addresses ----
    const u32 aHi = sb + SO_A + wid * A_ITEM;
    const u32 aLo = aHi + 32 * BST * 2;
    const u32 bHi = sb + SO_BHI;
    const u32 bLo = sb + SO_BLO;

    const int ar  = lane & 15;            // A row within 16
    const int ac  = (lane >> 4) * 8;      // A col half
    const int br  = lane & 7;             // B row within 8
    const int bc  = ((lane >> 3) & 1) * 8;

    float acc[2][8][4];
#pragma unroll
    for (int mt = 0; mt < 2; mt++)
#pragma unroll
        for (int nt = 0; nt < 8; nt++)
#pragma unroll
            for (int q = 0; q < 4; q++) acc[mt][nt][q] = 0.f;

#pragma unroll
    for (int kt = 0; kt < 4; kt++) {
        u32 ah[2][4], al[2][4];
#pragma unroll
        for (int mt = 0; mt < 2; mt++) {
            u32 off = (u32)(((mt * 16 + ar) * BST + kt * 16 + ac) * 2);
            ldsm_x4(ah[mt], aHi + off);
            ldsm_x4(al[mt], aLo + off);
        }
        u32 bh[8][2], bl[8][2];
#pragma unroll
        for (int nt = 0; nt < 8; nt++) {
            u32 off = (u32)(((nt * 8 + br) * BST + kt * 16 + bc) * 2);
            ldsm_x2(bh[nt], bHi + off);
            ldsm_x2(bl[nt], bLo + off);
        }
#pragma unroll
        for (int mt = 0; mt < 2; mt++)
#pragma unroll
            for (int nt = 0; nt < 8; nt++) {
                mma_bf16(acc[mt][nt], ah[mt], bh[nt]);
                mma_bf16(acc[mt][nt], ah[mt], bl[nt]);
                mma_bf16(acc[mt][nt], al[mt], bh[nt]);
            }
    }

    // ---- epilogue: add coarse vector, store pos<25 ----
    if (item < total) {
        float* ob = out + (size_t)item * (WW * DF);
        const float* ccb = g_cc + (size_t)item * DF;
        int colq = (lane & 3) * 2;
        int rowq = lane >> 2;
#pragma unroll
        for (int nt = 0; nt < 8; nt++) {
            int col = nt * 8 + colq;
            float2 cc = *(const float2*)(ccb + col);   // L1-hot broadcast
#pragma unroll
            for (int mt = 0; mt < 2; mt++) {
                int r0 = mt * 16 + rowq;
                if (r0 < WW) {
                    float2 o = make_float2(acc[mt][nt][0] + cc.x, acc[mt][nt][1] + cc.y);
                    *(float2*)(ob + r0 * DF + col) = o;
                }
                int r1 = r0 + 8;
                if (r1 < WW) {
                    float2 o = make_float2(acc[mt][nt][2] + cc.x, acc[mt][nt][3] + cc.y);
                    *(float2*)(ob + r1 * DF + col) = o;
                }
            }
        }
    }
}

extern "C" void kernel_launch(void* const* d_in, const int* in_sizes, int n_in,
                              void* d_out, int out_size) {
    const float* f0    = (const float*)d_in[0];
    const float* f1    = (const float*)d_in[1];
    const float* c0    = (const float*)d_in[2];
    const float* c1    = (const float*)d_in[3];
    const float* Wd    = (const float*)d_in[4];
    const float* bd    = (const float*)d_in[5];
    const float* Wm    = (const float*)d_in[6];
    const float* bm    = (const float*)d_in[7];
    const int*   b_ids = (const int*)d_in[8];
    const int*   cy    = (const int*)d_in[9];
    const int*   cx    = (const int*)d_in[10];
    const int*   ci    = (const int*)d_in[11];
    float* out = (float*)d_out;

    int N = in_sizes[8];
    int total = 2 * N;

    fuse_weights_kernel<<<DC, DF>>>(Wd, Wm, bd, bm);
    prep_B_kernel<<<DF, DF>>>(Wm);

    int cblocks = (total + CB_ITEMS - 1) / CB_ITEMS;
    coarse_kernel<<<cblocks, 128>>>(c0, c1, b_ids, ci, N);

    static int smem_set = 0;
    if (!smem_set) {
        cudaFuncSetAttribute(fine_main_kernel,
                             cudaFuncAttributeMaxDynamicSharedMemorySize, SMEM_TOTAL);
        smem_set = 1;
    }
    int mblocks = (total + 3) / 4;
    fine_main_kernel<<<mblocks, 128, SMEM_TOTAL>>>(f0, f1, b_ids, cy, cx, out, N);
}

// round 5
// speedup vs baseline: 1.3300x; 1.3300x over previous
#include <cuda_runtime.h>
#include <cuda_bf16.h>
#include <cstdint>

#define DF   64
#define DC   256
#define HF   240
#define WF   320
#define HW   (HF*WF)
#define LC   4800
#define WW   25
#define NMAX 16384
#define BST  72        // B bf16 row stride (144B, conflict-free ldmatrix)

typedef unsigned long long u64;
typedef unsigned int u32;
typedef unsigned short u16;

__device__ float g_Wfused[DC * DF];
__device__ float g_biasf[DF];
__device__ float g_cc[2 * NMAX * DF];
__device__ u16   g_Bhi[DF * BST];
__device__ u16   g_Blo[DF * BST];

// ================= helpers =================
__device__ __forceinline__ u64 ffma2(u64 a, u64 b, u64 c) {
    u64 d; asm("fma.rn.f32x2 %0, %1, %2, %3;" : "=l"(d) : "l"(a), "l"(b), "l"(c)); return d;
}
__device__ __forceinline__ u64 dup2(float x) {
    u64 d; asm("mov.b64 %0, {%1, %1};" : "=l"(d) : "f"(x)); return d;
}
__device__ __forceinline__ u64 pk2(float a, float b) {
    u64 d; asm("mov.b64 %0, {%1, %2};" : "=l"(d) : "f"(a), "f"(b)); return d;
}
__device__ __forceinline__ float2 up2(u64 v) {
    float2 r; asm("mov.b64 {%0, %1}, %2;" : "=f"(r.x), "=f"(r.y) : "l"(v)); return r;
}
__device__ __forceinline__ u32 smem_u32(const void* p) {
    u32 a; asm("{ .reg .u64 t; cvta.to.shared.u64 t, %1; cvt.u32.u64 %0, t; }" : "=r"(a) : "l"(p));
    return a;
}
__device__ __forceinline__ void ldsm_x4(u32* r, u32 addr) {
    asm volatile("ldmatrix.sync.aligned.m8n8.x4.shared.b16 {%0,%1,%2,%3}, [%4];"
                 : "=r"(r[0]), "=r"(r[1]), "=r"(r[2]), "=r"(r[3]) : "r"(addr));
}
__device__ __forceinline__ void mma_bf16(float* d, const u32* a, const u32* b) {
    asm volatile("mma.sync.aligned.m16n8k16.row.col.f32.bf16.bf16.f32 "
                 "{%0,%1,%2,%3}, {%4,%5,%6,%7}, {%8,%9}, {%0,%1,%2,%3};"
                 : "+f"(d[0]), "+f"(d[1]), "+f"(d[2]), "+f"(d[3])
                 : "r"(a[0]), "r"(a[1]), "r"(a[2]), "r"(a[3]), "r"(b[0]), "r"(b[1]));
}
// d = {hi16 = bf16(hi), lo16 = bf16(lo)}
__device__ __forceinline__ u32 packbf(float hi, float lo) {
    u32 d; asm("cvt.rn.bf16x2.f32 %0, %1, %2;" : "=r"(d) : "f"(hi), "f"(lo)); return d;
}

#define CP4(dst, src)  asm volatile("cp.async.ca.shared.global [%0], [%1], 4;"  :: "r"(dst), "l"(src))
#define CP16(dst, src) asm volatile("cp.async.cg.shared.global [%0], [%1], 16;" :: "r"(dst), "l"(src))
#define CP_COMMIT()    asm volatile("cp.async.commit_group;")
#define CP_WAIT0()     asm volatile("cp.async.wait_group 0;" ::: "memory")

// ================= weight fusion =================
__global__ void fuse_weights_kernel(const float* __restrict__ Wd,
                                    const float* __restrict__ Wm,
                                    const float* __restrict__ bd,
                                    const float* __restrict__ bm) {
    int i = blockIdx.x, j = threadIdx.x;
    float acc = 0.f;
#pragma unroll
    for (int k = 0; k < DF; k++)
        acc += Wd[i * DF + k] * Wm[(DF + k) * DF + j];
    g_Wfused[i * DF + j] = acc;
    if (i == 0) {
        float b = bm[j];
#pragma unroll
        for (int k = 0; k < DF; k++)
            b += bd[k] * Wm[(DF + k) * DF + j];
        g_biasf[j] = b;
    }
}

// B[n][k] = Wm_top[k][n], bf16 hi/lo, padded stride
__global__ void prep_B_kernel(const float* __restrict__ Wm) {
    int n = blockIdx.x, k = threadIdx.x;
    float v = Wm[k * DF + n];
    __nv_bfloat16 h = __float2bfloat16(v);
    float lo = v - __bfloat162float(h);
    __nv_bfloat16 l = __float2bfloat16(lo);
    g_Bhi[n * BST + k] = *(u16*)&h;
    g_Blo[n * BST + k] = *(u16*)&l;
}

// ================= coarse projection v2 (smem-cached Wfused) =================
#define CO_ITEMS 32
#define CO_CVSTR 260                       // f32 stride; 1040B, 16B aligned
#define CO_SWF   0                         // 65536 B
#define CO_SCV   65536                     // 32*260*4 = 33280 B
#define CO_SMEM  (65536 + CO_ITEMS * CO_CVSTR * 4)

__global__ __launch_bounds__(128) void coarse_kernel(
    const float* __restrict__ c0, const float* __restrict__ c1,
    const int* __restrict__ b_ids, const int* __restrict__ ci, int N)
{
    extern __shared__ char csm[];
    const u32 csb = smem_u32(csm);
    float* sWf = (float*)csm;
    float* sCv = (float*)(csm + CO_SCV);
    __shared__ int s_off[CO_ITEMS];
    __shared__ const float* s_ptr[CO_ITEMS];

    int tid = threadIdx.x;
    int base = blockIdx.x * CO_ITEMS;
    int total = 2 * N;

    if (tid < CO_ITEMS) {
        int item = base + tid;
        if (item >= total) item = total - 1;
        int s = item >= N;
        int p = item - s * N;
        s_ptr[tid] = s ? c1 : c0;
        s_off[tid] = (__ldg(b_ids + p) * LC + __ldg(ci + p)) * DC;
    }
    __syncthreads();

    // stage Wfused (64 KB) + coarse vectors (32 KB) via cp.async
    {
        const char* wsrc = (const char*)g_Wfused;
#pragma unroll
        for (int i = 0; i < 32; i++)
            CP16(csb + CO_SWF + tid * 16 + i * 2048, wsrc + tid * 16 + i * 2048);
        for (int c = tid; c < CO_ITEMS * 64; c += 128) {
            int it = c >> 6, k16 = c & 63;
            const float* src = s_ptr[it] + s_off[it] + k16 * 4;
            CP16(csb + CO_SCV + it * (CO_CVSTR * 4) + k16 * 16, src);
        }
    }
    CP_COMMIT();
    CP_WAIT0();
    __syncthreads();

    int ig = tid >> 4, cgp = tid & 15;
    u64 acc[4][2];
#pragma unroll
    for (int m = 0; m < 4; m++) { acc[m][0] = 0ull; acc[m][1] = 0ull; }
    const float* cv0 = sCv + (4 * ig) * CO_CVSTR;
    const float4* wv = (const float4*)sWf + cgp;

#pragma unroll 4
    for (int k = 0; k < DC; k++) {
        float4 w = wv[k * 16];
        u64 w0 = pk2(w.x, w.y), w1 = pk2(w.z, w.w);
#pragma unroll
        for (int m = 0; m < 4; m++) {
            u64 a = dup2(cv0[m * CO_CVSTR + k]);
            acc[m][0] = ffma2(a, w0, acc[m][0]);
            acc[m][1] = ffma2(a, w1, acc[m][1]);
        }
    }
    float b0 = g_biasf[cgp * 4], b1 = g_biasf[cgp * 4 + 1];
    float b2 = g_biasf[cgp * 4 + 2], b3 = g_biasf[cgp * 4 + 3];
#pragma unroll
    for (int m = 0; m < 4; m++) {
        int item = base + 4 * ig + m;
        if (item < total) {
            float2 x0 = up2(acc[m][0]), x1 = up2(acc[m][1]);
            *(float4*)(g_cc + (size_t)item * DF + cgp * 4) =
                make_float4(x0.x + b0, x0.y + b1, x1.x + b2, x1.y + b3);
        }
    }
}

// ================= main kernel =================
// smem: B hi (9216) | B lo (9216) | A f32 tiles: 4 items x 8192
#define SO_BHI 0
#define SO_BLO 9216
#define SO_A   18432
#define SMEM_TOTAL (18432 + 4 * 8192)   // 51200

__global__ __launch_bounds__(128, 4) void fine_main_kernel(
    const float* __restrict__ f0, const float* __restrict__ f1,
    const int* __restrict__ b_ids, const int* __restrict__ cy,
    const int* __restrict__ cx,
    float* __restrict__ out, int N)
{
    extern __shared__ char smem[];
    const u32 sb = smem_u32(smem);
    const int tid = threadIdx.x;
    const int wid = tid >> 5;
    const int lane = tid & 31;
    const int total = 2 * N;

    // ---- stage B hi/lo via cp.async ----
    {
        const char* srcH = (const char*)g_Bhi;
        const char* srcL = (const char*)g_Blo;
        for (int i = tid * 16; i < DF * BST * 2; i += 128 * 16) {
            CP16(sb + SO_BHI + i, srcH + i);
            CP16(sb + SO_BLO + i, srcL + i);
        }
    }

    // ---- gather A window (f32, parity-interleaved chunks) via cp.async ----
    int item = blockIdx.x * 4 + wid;
    int itemc = item < total ? item : total - 1;
    {
        int s = itemc >= N;
        int p = itemc - s * N;
        const float* fsrc = s ? f1 : f0;
        int b = __ldg(b_ids + p), y = __ldg(cy + p), x = __ldg(cx + p);
        const float* fbase = fsrc + (size_t)b * (DF * HW) + (size_t)(y - 2) * WF + (x - 2);

        const int cl = lane >> 3, pl = lane & 7;
        int offs[4];
        bool val[4];
#pragma unroll
        for (int sI = 0; sI < 4; sI++) {
            int pos = pl + 8 * sI;
            val[sI] = pos < WW;
            int dy = pos / 5;
            offs[sI] = dy * WF + (pos - dy * 5);
        }
        const u32 aItem = sb + SO_A + wid * 8192;
        const float* src = fbase + cl * 16 * HW;
#pragma unroll
        for (int t = 0; t < 16; t++) {
            u32 dstb = aItem
                     + (u32)(cl * 4 + ((t >> 3) << 1) + (t & 1)) * 512
                     + (u32)(((t >> 1) & 3) * 4)
                     + (u32)(pl * 16);
#pragma unroll
            for (int sI = 0; sI < 4; sI++)
                if (val[sI]) CP4(dstb + sI * 128, src + offs[sI]);
            src += HW;
        }
    }
    CP_COMMIT();
    CP_WAIT0();
    __syncthreads();

    // ---- 32x64x64 GEMM, bf16 3-term split, fragments built in regs ----
    const u32 aItem = sb + SO_A + wid * 8192;
    float acc[2][8][4];
#pragma unroll
    for (int mt = 0; mt < 2; mt++)
#pragma unroll
        for (int nt = 0; nt < 8; nt++)
#pragma unroll
            for (int q = 0; q < 4; q++) acc[mt][nt][q] = 0.f;

    const u32 aLaneOff = (u32)((lane >> 4) * 512 + (lane & 15) * 16);
    const u32 bRow = (u32)((((lane >> 4) & 1) * 8 + (lane & 7)) * (BST * 2));
    const u32 bCol = (u32)(((lane >> 3) & 1) * 16);

#pragma unroll
    for (int kt = 0; kt < 4; kt++) {
        u32 ah[2][4], al[2][4];
#pragma unroll
        for (int mt = 0; mt < 2; mt++) {
#pragma unroll
            for (int kh = 0; kh < 2; kh++) {
                u32 addr = aItem + (u32)(kt * 4 + kh * 2) * 512
                         + (u32)(mt * 16 * 16) + aLaneOff;
                u32 r[4];
                ldsm_x4(r, addr);
                float v00 = __uint_as_float(r[0]);
                float v10 = __uint_as_float(r[1]);
                float v01 = __uint_as_float(r[2]);
                float v11 = __uint_as_float(r[3]);
                u32 h0 = packbf(v01, v00);
                u32 h1 = packbf(v11, v10);
                float h00 = __uint_as_float(h0 << 16);
                float h01 = __uint_as_float(h0 & 0xffff0000u);
                float h10 = __uint_as_float(h1 << 16);
                float h11 = __uint_as_float(h1 & 0xffff0000u);
                u32 l0 = packbf(v01 - h01, v00 - h00);
                u32 l1 = packbf(v11 - h11, v10 - h10);
                ah[mt][kh * 2 + 0] = h0;
                ah[mt][kh * 2 + 1] = h1;
                al[mt][kh * 2 + 0] = l0;
                al[mt][kh * 2 + 1] = l1;
            }
        }
#pragma unroll
        for (int half = 0; half < 2; half++) {
            u32 bh[2][4], bl[2][4];
#pragma unroll
            for (int ntp = 0; ntp < 2; ntp++) {
                u32 rowBase = (u32)((half * 2 + ntp) * 16 * (BST * 2));
                u32 baddr = rowBase + bRow + (u32)(kt * 32) + bCol;
                ldsm_x4(bh[ntp], sb + SO_BHI + baddr);
                ldsm_x4(bl[ntp], sb + SO_BLO + baddr);
            }
#pragma unroll
            for (int ntp = 0; ntp < 2; ntp++) {
#pragma unroll
                for (int sub = 0; sub < 2; sub++) {
                    int nt = half * 4 + ntp * 2 + sub;
                    u32 bhp[2] = {bh[ntp][sub * 2], bh[ntp][sub * 2 + 1]};
                    u32 blp[2] = {bl[ntp][sub * 2], bl[ntp][sub * 2 + 1]};
#pragma unroll
                    for (int mt = 0; mt < 2; mt++) {
                        mma_bf16(acc[mt][nt], ah[mt], bhp);
                        mma_bf16(acc[mt][nt], ah[mt], blp);
                        mma_bf16(acc[mt][nt], al[mt], bhp);
                    }
                }
            }
        }
    }

    // ---- epilogue: add coarse vector, store pos<25 ----
    if (item < total) {
        const int g = lane >> 2, jc = (lane & 3) * 2;
        float2 cc[8];
        const float* ccb = g_cc + (size_t)item * DF + jc;
#pragma unroll
        for (int nt = 0; nt < 8; nt++)
            cc[nt] = *(const float2*)(ccb + nt * 8);

        float* ob = out + (size_t)item * (WW * DF) + jc;
#pragma unroll
        for (int nt = 0; nt < 8; nt++) {
#pragma unroll
            for (int mt = 0; mt < 2; mt++) {
                int r0 = mt * 16 + g;
                *(float2*)(ob + r0 * DF + nt * 8) =
                    make_float2(acc[mt][nt][0] + cc[nt].x, acc[mt][nt][1] + cc[nt].y);
                if (mt == 0 || g == 0) {
                    int r1 = r0 + 8;
                    *(float2*)(ob + r1 * DF + nt * 8) =
                        make_float2(acc[mt][nt][2] + cc[nt].x, acc[mt][nt][3] + cc[nt].y);
                }
            }
        }
    }
}

extern "C" void kernel_launch(void* const* d_in, const int* in_sizes, int n_in,
                              void* d_out, int out_size) {
    const float* f0    = (const float*)d_in[0];
    const float* f1    = (const float*)d_in[1];
    const float* c0    = (const float*)d_in[2];
    const float* c1    = (const float*)d_in[3];
    const float* Wd    = (const float*)d_in[4];
    const float* bd    = (const float*)d_in[5];
    const float* Wm    = (const float*)d_in[6];
    const float* bm    = (const float*)d_in[7];
    const int*   b_ids = (const int*)d_in[8];
    const int*   cy    = (const int*)d_in[9];
    const int*   cx    = (const int*)d_in[10];
    const int*   ci    = (const int*)d_in[11];
    float* out = (float*)d_out;

    int N = in_sizes[8];
    int total = 2 * N;

    fuse_weights_kernel<<<DC, DF>>>(Wd, Wm, bd, bm);
    prep_B_kernel<<<DF, DF>>>(Wm);

    cudaFuncSetAttribute(coarse_kernel,
                         cudaFuncAttributeMaxDynamicSharedMemorySize, CO_SMEM);
    int cblocks = (total + CO_ITEMS - 1) / CO_ITEMS;
    coarse_kernel<<<cblocks, 128, CO_SMEM>>>(c0, c1, b_ids, ci, N);

    cudaFuncSetAttribute(fine_main_kernel,
                         cudaFuncAttributeMaxDynamicSharedMemorySize, SMEM_TOTAL);
    int mblocks = (total + 3) / 4;
    fine_main_kernel<<<mblocks, 128, SMEM_TOTAL>>>(f0, f1, b_ids, cy, cx, out, N);
}

// round 6
// speedup vs baseline: 1.7015x; 1.2793x over previous
#include <cuda_runtime.h>
#include <cuda_bf16.h>
#include <cstdint>

#define DF   64
#define DC   256
#define HF   240
#define WF   320
#define HW   (HF*WF)
#define LC   4800
#define WW   25
#define NMAX 16384
#define BST  72        // B bf16 row stride (144B, conflict-free ldmatrix)

typedef unsigned long long u64;
typedef unsigned int u32;
typedef unsigned short u16;

__device__ float g_Wfused[DC * DF];
__device__ float g_biasf[DF];
__device__ float g_cc[2 * NMAX * DF];
__device__ u16   g_Bhi[DF * BST];
__device__ u16   g_Blo[DF * BST];

// ================= helpers =================
__device__ __forceinline__ u64 ffma2(u64 a, u64 b, u64 c) {
    u64 d; asm("fma.rn.f32x2 %0, %1, %2, %3;" : "=l"(d) : "l"(a), "l"(b), "l"(c)); return d;
}
__device__ __forceinline__ u64 dup2(float x) {
    u64 d; asm("mov.b64 %0, {%1, %1};" : "=l"(d) : "f"(x)); return d;
}
__device__ __forceinline__ u64 pk2(float a, float b) {
    u64 d; asm("mov.b64 %0, {%1, %2};" : "=l"(d) : "f"(a), "f"(b)); return d;
}
__device__ __forceinline__ float2 up2(u64 v) {
    float2 r; asm("mov.b64 {%0, %1}, %2;" : "=f"(r.x), "=f"(r.y) : "l"(v)); return r;
}
__device__ __forceinline__ u32 smem_u32(const void* p) {
    u32 a; asm("{ .reg .u64 t; cvta.to.shared.u64 t, %1; cvt.u32.u64 %0, t; }" : "=r"(a) : "l"(p));
    return a;
}
__device__ __forceinline__ void ldsm_x4(u32* r, u32 addr) {
    asm volatile("ldmatrix.sync.aligned.m8n8.x4.shared.b16 {%0,%1,%2,%3}, [%4];"
                 : "=r"(r[0]), "=r"(r[1]), "=r"(r[2]), "=r"(r[3]) : "r"(addr));
}
__device__ __forceinline__ void mma_bf16(float* d, const u32* a, const u32* b) {
    asm volatile("mma.sync.aligned.m16n8k16.row.col.f32.bf16.bf16.f32 "
                 "{%0,%1,%2,%3}, {%4,%5,%6,%7}, {%8,%9}, {%0,%1,%2,%3};"
                 : "+f"(d[0]), "+f"(d[1]), "+f"(d[2]), "+f"(d[3])
                 : "r"(a[0]), "r"(a[1]), "r"(a[2]), "r"(a[3]), "r"(b[0]), "r"(b[1]));
}
__device__ __forceinline__ u32 packbf(float hi, float lo) {
    u32 d; asm("cvt.rn.bf16x2.f32 %0, %1, %2;" : "=r"(d) : "f"(hi), "f"(lo)); return d;
}

#define CP4(dst, src)  asm volatile("cp.async.ca.shared.global [%0], [%1], 4;"  :: "r"(dst), "l"(src))
#define CP16(dst, src) asm volatile("cp.async.cg.shared.global [%0], [%1], 16;" :: "r"(dst), "l"(src))
#define CP_COMMIT()    asm volatile("cp.async.commit_group;")
#define CP_WAIT0()     asm volatile("cp.async.wait_group 0;" ::: "memory")
#define CP_WAIT1()     asm volatile("cp.async.wait_group 1;" ::: "memory")

// ================= weight fusion =================
__global__ void fuse_weights_kernel(const float* __restrict__ Wd,
                                    const float* __restrict__ Wm,
                                    const float* __restrict__ bd,
                                    const float* __restrict__ bm) {
    int i = blockIdx.x, j = threadIdx.x;
    float acc = 0.f;
#pragma unroll
    for (int k = 0; k < DF; k++)
        acc += Wd[i * DF + k] * Wm[(DF + k) * DF + j];
    g_Wfused[i * DF + j] = acc;
    if (i == 0) {
        float b = bm[j];
#pragma unroll
        for (int k = 0; k < DF; k++)
            b += bd[k] * Wm[(DF + k) * DF + j];
        g_biasf[j] = b;
    }
}

__global__ void prep_B_kernel(const float* __restrict__ Wm) {
    int n = blockIdx.x, k = threadIdx.x;
    float v = Wm[k * DF + n];
    __nv_bfloat16 h = __float2bfloat16(v);
    float lo = v - __bfloat162float(h);
    __nv_bfloat16 l = __float2bfloat16(lo);
    g_Bhi[n * BST + k] = *(u16*)&h;
    g_Blo[n * BST + k] = *(u16*)&l;
}

// ================= coarse projection (smem-cached Wfused) =================
#define CO_ITEMS 32
#define CO_CVSTR 260
#define CO_SCV   65536
#define CO_SMEM  (65536 + CO_ITEMS * CO_CVSTR * 4)

__global__ __launch_bounds__(128) void coarse_kernel(
    const float* __restrict__ c0, const float* __restrict__ c1,
    const int* __restrict__ b_ids, const int* __restrict__ ci, int N)
{
    extern __shared__ char csm[];
    const u32 csb = smem_u32(csm);
    float* sWf = (float*)csm;
    float* sCv = (float*)(csm + CO_SCV);
    __shared__ int s_off[CO_ITEMS];
    __shared__ const float* s_ptr[CO_ITEMS];

    int tid = threadIdx.x;
    int base = blockIdx.x * CO_ITEMS;
    int total = 2 * N;

    if (tid < CO_ITEMS) {
        int item = base + tid;
        if (item >= total) item = total - 1;
        int s = item >= N;
        int p = item - s * N;
        s_ptr[tid] = s ? c1 : c0;
        s_off[tid] = (__ldg(b_ids + p) * LC + __ldg(ci + p)) * DC;
    }
    __syncthreads();

    {
        const char* wsrc = (const char*)g_Wfused;
#pragma unroll
        for (int i = 0; i < 32; i++)
            CP16(csb + tid * 16 + i * 2048, wsrc + tid * 16 + i * 2048);
        for (int c = tid; c < CO_ITEMS * 64; c += 128) {
            int it = c >> 6, k16 = c & 63;
            const float* src = s_ptr[it] + s_off[it] + k16 * 4;
            CP16(csb + CO_SCV + it * (CO_CVSTR * 4) + k16 * 16, src);
        }
    }
    CP_COMMIT();
    CP_WAIT0();
    __syncthreads();

    int ig = tid >> 4, cgp = tid & 15;
    u64 acc[4][2];
#pragma unroll
    for (int m = 0; m < 4; m++) { acc[m][0] = 0ull; acc[m][1] = 0ull; }
    const float* cv0 = sCv + (4 * ig) * CO_CVSTR;
    const float4* wv = (const float4*)sWf + cgp;

#pragma unroll 4
    for (int k = 0; k < DC; k++) {
        float4 w = wv[k * 16];
        u64 w0 = pk2(w.x, w.y), w1 = pk2(w.z, w.w);
#pragma unroll
        for (int m = 0; m < 4; m++) {
            u64 a = dup2(cv0[m * CO_CVSTR + k]);
            acc[m][0] = ffma2(a, w0, acc[m][0]);
            acc[m][1] = ffma2(a, w1, acc[m][1]);
        }
    }
    float b0 = g_biasf[cgp * 4], b1 = g_biasf[cgp * 4 + 1];
    float b2 = g_biasf[cgp * 4 + 2], b3 = g_biasf[cgp * 4 + 3];
#pragma unroll
    for (int m = 0; m < 4; m++) {
        int item = base + 4 * ig + m;
        if (item < total) {
            float2 x0 = up2(acc[m][0]), x1 = up2(acc[m][1]);
            *(float4*)(g_cc + (size_t)item * DF + cgp * 4) =
                make_float4(x0.x + b0, x0.y + b1, x1.x + b2, x1.y + b3);
        }
    }
}

// ================= main kernel: persistent + pipelined =================
// smem: B hi (9216) | B lo (9216) | A bufs: 4 warps x 2 bufs x 8192
#define SO_BHI 0
#define SO_BLO 9216
#define SO_A   18432
#define SMEM_TOTAL (18432 + 4 * 2 * 8192)   // 83968

__global__ __launch_bounds__(128) void fine_main_kernel(
    const float* __restrict__ f0, const float* __restrict__ f1,
    const int* __restrict__ b_ids, const int* __restrict__ cy,
    const int* __restrict__ cx,
    float* __restrict__ out, int N)
{
    extern __shared__ char smem[];
    const u32 sb = smem_u32(smem);
    const int tid = threadIdx.x;
    const int wid = tid >> 5;
    const int lane = tid & 31;
    const int total = 2 * N;
    const int nGroups = (total + 3) >> 2;

    // per-thread gather constants (hoisted out of item loop)
    const int cl = lane >> 3, pl = lane & 7;
    int offs[4];
    bool val[4];
#pragma unroll
    for (int sI = 0; sI < 4; sI++) {
        int pos = pl + 8 * sI;
        val[sI] = pos < WW;
        int dy = pos / 5;
        offs[sI] = dy * WF + (pos - dy * 5);
    }
    u32 dstc[16];
#pragma unroll
    for (int t = 0; t < 16; t++)
        dstc[t] = (u32)(cl * 4 + ((t >> 3) << 1) + (t & 1)) * 512
                + (u32)(((t >> 1) & 3) * 4) + (u32)(pl * 16);

    const u32 abuf0 = sb + SO_A + wid * 16384;

    // gather lambda
    auto gather = [&](int item, u32 aAddr) {
        int s = item >= N;
        int p = item - s * N;
        const float* fsrc = s ? f1 : f0;
        int b = __ldg(b_ids + p), y = __ldg(cy + p), x = __ldg(cx + p);
        const float* fbase = fsrc + (size_t)b * (DF * HW) + (size_t)(y - 2) * WF + (x - 2)
                           + cl * 16 * HW;
#pragma unroll
        for (int t = 0; t < 16; t++) {
            u32 dstb = aAddr + dstc[t];
            const float* src = fbase + t * HW;
#pragma unroll
            for (int sI = 0; sI < 4; sI++)
                if (val[sI]) CP4(dstb + sI * 128, src + offs[sI]);
        }
    };

    // ---- stage B (group 0) ----
    {
        const char* srcH = (const char*)g_Bhi;
        const char* srcL = (const char*)g_Blo;
        for (int i = tid * 16; i < DF * BST * 2; i += 128 * 16) {
            CP16(sb + SO_BHI + i, srcH + i);
            CP16(sb + SO_BLO + i, srcL + i);
        }
    }
    CP_COMMIT();

    int group = blockIdx.x;
    if (group >= nGroups) return;

    // ---- prologue: gather first item (group 1) ----
    {
        int it0 = group * 4 + wid;
        if (it0 >= total) it0 = total - 1;
        gather(it0, abuf0);
    }
    CP_COMMIT();
    CP_WAIT1();        // B ready
    __syncthreads();

    const u32 aLaneOff = (u32)((lane >> 4) * 512 + (lane & 15) * 16);
    const u32 bRow = (u32)((((lane >> 4) & 1) * 8 + (lane & 7)) * (BST * 2));
    const u32 bCol = (u32)(((lane >> 3) & 1) * 16);
    const int g = lane >> 2, jc = (lane & 3) * 2;

    int buf = 0;
    while (group < nGroups) {
        int nextGroup = group + gridDim.x;
        int item = group * 4 + wid;

        // issue next gather into other buffer
        {
            int ni = nextGroup * 4 + wid;
            if (ni >= total) ni = total - 1;
            gather(ni, abuf0 + (u32)((buf ^ 1) * 8192));
        }
        CP_COMMIT();
        CP_WAIT1();    // current buffer's group complete
        __syncwarp();

        // prefetch coarse vector (clamped)
        int itemc = item < total ? item : total - 1;
        float2 cc[8];
        {
            const float* ccb = g_cc + (size_t)itemc * DF + jc;
#pragma unroll
            for (int nt = 0; nt < 8; nt++)
                cc[nt] = *(const float2*)(ccb + nt * 8);
        }

        // ---- 32x64x64 GEMM, bf16 3-term split ----
        const u32 aItem = abuf0 + (u32)(buf * 8192);
        float acc[2][8][4];
#pragma unroll
        for (int mt = 0; mt < 2; mt++)
#pragma unroll
            for (int nt = 0; nt < 8; nt++)
#pragma unroll
                for (int q = 0; q < 4; q++) acc[mt][nt][q] = 0.f;

#pragma unroll
        for (int kt = 0; kt < 4; kt++) {
            u32 ah[2][4], al[2][4];
#pragma unroll
            for (int mt = 0; mt < 2; mt++) {
#pragma unroll
                for (int kh = 0; kh < 2; kh++) {
                    u32 addr = aItem + (u32)(kt * 4 + kh * 2) * 512
                             + (u32)(mt * 16 * 16) + aLaneOff;
                    u32 r[4];
                    ldsm_x4(r, addr);
                    float v00 = __uint_as_float(r[0]);
                    float v10 = __uint_as_float(r[1]);
                    float v01 = __uint_as_float(r[2]);
                    float v11 = __uint_as_float(r[3]);
                    u32 h0 = packbf(v01, v00);
                    u32 h1 = packbf(v11, v10);
                    float h00 = __uint_as_float(h0 << 16);
                    float h01 = __uint_as_float(h0 & 0xffff0000u);
                    float h10 = __uint_as_float(h1 << 16);
                    float h11 = __uint_as_float(h1 & 0xffff0000u);
                    u32 l0 = packbf(v01 - h01, v00 - h00);
                    u32 l1 = packbf(v11 - h11, v10 - h10);
                    ah[mt][kh * 2 + 0] = h0;
                    ah[mt][kh * 2 + 1] = h1;
                    al[mt][kh * 2 + 0] = l0;
                    al[mt][kh * 2 + 1] = l1;
                }
            }
#pragma unroll
            for (int half = 0; half < 2; half++) {
                u32 bh[2][4], bl[2][4];
#pragma unroll
                for (int ntp = 0; ntp < 2; ntp++) {
                    u32 rowBase = (u32)((half * 2 + ntp) * 16 * (BST * 2));
                    u32 baddr = rowBase + bRow + (u32)(kt * 32) + bCol;
                    ldsm_x4(bh[ntp], sb + SO_BHI + baddr);
                    ldsm_x4(bl[ntp], sb + SO_BLO + baddr);
                }
#pragma unroll
                for (int ntp = 0; ntp < 2; ntp++) {
#pragma unroll
                    for (int sub = 0; sub < 2; sub++) {
                        int nt = half * 4 + ntp * 2 + sub;
                        u32 bhp[2] = {bh[ntp][sub * 2], bh[ntp][sub * 2 + 1]};
                        u32 blp[2] = {bl[ntp][sub * 2], bl[ntp][sub * 2 + 1]};
#pragma unroll
                        for (int mt = 0; mt < 2; mt++) {
                            mma_bf16(acc[mt][nt], ah[mt], bhp);
                            mma_bf16(acc[mt][nt], ah[mt], blp);
                            mma_bf16(acc[mt][nt], al[mt], bhp);
                        }
                    }
                }
            }
        }

        // ---- epilogue ----
        if (item < total) {
            float* ob = out + (size_t)item * (WW * DF) + jc;
#pragma unroll
            for (int nt = 0; nt < 8; nt++) {
#pragma unroll
                for (int mt = 0; mt < 2; mt++) {
                    int r0 = mt * 16 + g;
                    *(float2*)(ob + r0 * DF + nt * 8) =
                        make_float2(acc[mt][nt][0] + cc[nt].x, acc[mt][nt][1] + cc[nt].y);
                    if (mt == 0 || g == 0) {
                        int r1 = r0 + 8;
                        *(float2*)(ob + r1 * DF + nt * 8) =
                            make_float2(acc[mt][nt][2] + cc[nt].x, acc[mt][nt][3] + cc[nt].y);
                    }
                }
            }
        }

        buf ^= 1;
        group = nextGroup;
    }
}

extern "C" void kernel_launch(void* const* d_in, const int* in_sizes, int n_in,
                              void* d_out, int out_size) {
    const float* f0    = (const float*)d_in[0];
    const float* f1    = (const float*)d_in[1];
    const float* c0    = (const float*)d_in[2];
    const float* c1    = (const float*)d_in[3];
    const float* Wd    = (const float*)d_in[4];
    const float* bd    = (const float*)d_in[5];
    const float* Wm    = (const float*)d_in[6];
    const float* bm    = (const float*)d_in[7];
    const int*   b_ids = (const int*)d_in[8];
    const int*   cy    = (const int*)d_in[9];
    const int*   cx    = (const int*)d_in[10];
    const int*   ci    = (const int*)d_in[11];
    float* out = (float*)d_out;

    int N = in_sizes[8];
    int total = 2 * N;

    fuse_weights_kernel<<<DC, DF>>>(Wd, Wm, bd, bm);
    prep_B_kernel<<<DF, DF>>>(Wm);

    static int attr_set = 0;
    if (!attr_set) {
        cudaFuncSetAttribute(coarse_kernel,
                             cudaFuncAttributeMaxDynamicSharedMemorySize, CO_SMEM);
        cudaFuncSetAttribute(fine_main_kernel,
                             cudaFuncAttributeMaxDynamicSharedMemorySize, SMEM_TOTAL);
        attr_set = 1;
    }

    int cblocks = (total + CO_ITEMS - 1) / CO_ITEMS;
    coarse_kernel<<<cblocks, 128, CO_SMEM>>>(c0, c1, b_ids, ci, N);

    int nGroups = (total + 3) / 4;
    int mblocks = 2 * 148;
    if (mblocks > nGroups) mblocks = nGroups;
    fine_main_kernel<<<mblocks, 128, SMEM_TOTAL>>>(f0, f1, b_ids, cy, cx, out, N);
}

// round 7
// speedup vs baseline: 2.0684x; 1.2157x over previous
#include <cuda_runtime.h>
#include <cuda_bf16.h>
#include <cstdint>

#define DF   64
#define DC   256
#define HF   240
#define WF   320
#define HW   (HF*WF)
#define LC   4800
#define WW   25
#define NMAX 16384
#define BST  72        // B bf16 row stride (144B, conflict-free ldmatrix)

typedef unsigned long long u64;
typedef unsigned int u32;
typedef unsigned short u16;

__device__ float g_Wfused[DC * DF];
__device__ float g_biasf[DF];
__device__ float g_cc[2 * NMAX * DF];
__device__ u16   g_Bhi[DF * BST];
__device__ u16   g_Blo[DF * BST];

// ================= helpers =================
__device__ __forceinline__ u64 ffma2(u64 a, u64 b, u64 c) {
    u64 d; asm("fma.rn.f32x2 %0, %1, %2, %3;" : "=l"(d) : "l"(a), "l"(b), "l"(c)); return d;
}
__device__ __forceinline__ u64 dup2(float x) {
    u64 d; asm("mov.b64 %0, {%1, %1};" : "=l"(d) : "f"(x)); return d;
}
__device__ __forceinline__ u64 pk2(float a, float b) {
    u64 d; asm("mov.b64 %0, {%1, %2};" : "=l"(d) : "f"(a), "f"(b)); return d;
}
__device__ __forceinline__ float2 up2(u64 v) {
    float2 r; asm("mov.b64 {%0, %1}, %2;" : "=f"(r.x), "=f"(r.y) : "l"(v)); return r;
}
__device__ __forceinline__ u32 smem_u32(const void* p) {
    u32 a; asm("{ .reg .u64 t; cvta.to.shared.u64 t, %1; cvt.u32.u64 %0, t; }" : "=r"(a) : "l"(p));
    return a;
}
__device__ __forceinline__ void ldsm_x4(u32* r, u32 addr) {
    asm volatile("ldmatrix.sync.aligned.m8n8.x4.shared.b16 {%0,%1,%2,%3}, [%4];"
                 : "=r"(r[0]), "=r"(r[1]), "=r"(r[2]), "=r"(r[3]) : "r"(addr));
}
__device__ __forceinline__ void mma_bf16(float* d, const u32* a, const u32* b) {
    asm volatile("mma.sync.aligned.m16n8k16.row.col.f32.bf16.bf16.f32 "
                 "{%0,%1,%2,%3}, {%4,%5,%6,%7}, {%8,%9}, {%0,%1,%2,%3};"
                 : "+f"(d[0]), "+f"(d[1]), "+f"(d[2]), "+f"(d[3])
                 : "r"(a[0]), "r"(a[1]), "r"(a[2]), "r"(a[3]), "r"(b[0]), "r"(b[1]));
}
__device__ __forceinline__ u32 packbf(float hi, float lo) {
    u32 d; asm("cvt.rn.bf16x2.f32 %0, %1, %2;" : "=r"(d) : "f"(hi), "f"(lo)); return d;
}

#define CP16(dst, src) asm volatile("cp.async.cg.shared.global [%0], [%1], 16;" :: "r"(dst), "l"(src))
#define CP_COMMIT()    asm volatile("cp.async.commit_group;")
#define CP_WAIT0()     asm volatile("cp.async.wait_group 0;" ::: "memory")

// ================= weight fusion =================
__global__ void fuse_weights_kernel(const float* __restrict__ Wd,
                                    const float* __restrict__ Wm,
                                    const float* __restrict__ bd,
                                    const float* __restrict__ bm) {
    int i = blockIdx.x, j = threadIdx.x;
    float acc = 0.f;
#pragma unroll
    for (int k = 0; k < DF; k++)
        acc += Wd[i * DF + k] * Wm[(DF + k) * DF + j];
    g_Wfused[i * DF + j] = acc;
    if (i == 0) {
        float b = bm[j];
#pragma unroll
        for (int k = 0; k < DF; k++)
            b += bd[k] * Wm[(DF + k) * DF + j];
        g_biasf[j] = b;
    }
}

__global__ void prep_B_kernel(const float* __restrict__ Wm) {
    int n = blockIdx.x, k = threadIdx.x;
    float v = Wm[k * DF + n];
    __nv_bfloat16 h = __float2bfloat16(v);
    float lo = v - __bfloat162float(h);
    __nv_bfloat16 l = __float2bfloat16(lo);
    g_Bhi[n * BST + k] = *(u16*)&h;
    g_Blo[n * BST + k] = *(u16*)&l;
}

// ================= coarse projection: 64 items/block =================
#define CO_ITEMS 64
#define CO_CVSTR 260
#define CO_SCV   65536
#define CO_SMEM  (65536 + CO_ITEMS * CO_CVSTR * 4)   // 132096

__global__ __launch_bounds__(256) void coarse_kernel(
    const float* __restrict__ c0, const float* __restrict__ c1,
    const int* __restrict__ b_ids, const int* __restrict__ ci, int N)
{
    extern __shared__ char csm[];
    const u32 csb = smem_u32(csm);
    float* sWf = (float*)csm;
    float* sCv = (float*)(csm + CO_SCV);
    __shared__ int s_off[CO_ITEMS];
    __shared__ const float* s_ptr[CO_ITEMS];

    int tid = threadIdx.x;
    int base = blockIdx.x * CO_ITEMS;
    int total = 2 * N;

    if (tid < CO_ITEMS) {
        int item = base + tid;
        if (item >= total) item = total - 1;
        int s = item >= N;
        int p = item - s * N;
        s_ptr[tid] = s ? c1 : c0;
        s_off[tid] = (__ldg(b_ids + p) * LC + __ldg(ci + p)) * DC;
    }
    __syncthreads();

    {
        const char* wsrc = (const char*)g_Wfused;
#pragma unroll
        for (int i = 0; i < 16; i++)
            CP16(csb + tid * 16 + i * 4096, wsrc + tid * 16 + i * 4096);
        for (int c = tid; c < CO_ITEMS * 64; c += 256) {
            int it = c >> 6, k16 = c & 63;
            const float* src = s_ptr[it] + s_off[it] + k16 * 4;
            CP16(csb + CO_SCV + it * (CO_CVSTR * 4) + k16 * 16, src);
        }
    }
    CP_COMMIT();
    CP_WAIT0();
    __syncthreads();

    int ig = tid >> 4, cgp = tid & 15;
    u64 acc[4][2];
#pragma unroll
    for (int m = 0; m < 4; m++) { acc[m][0] = 0ull; acc[m][1] = 0ull; }
    const float* cv0 = sCv + (4 * ig) * CO_CVSTR;
    const float4* wv = (const float4*)sWf + cgp;

#pragma unroll 4
    for (int k = 0; k < DC; k++) {
        float4 w = wv[k * 16];
        u64 w0 = pk2(w.x, w.y), w1 = pk2(w.z, w.w);
#pragma unroll
        for (int m = 0; m < 4; m++) {
            u64 a = dup2(cv0[m * CO_CVSTR + k]);
            acc[m][0] = ffma2(a, w0, acc[m][0]);
            acc[m][1] = ffma2(a, w1, acc[m][1]);
        }
    }
    float b0 = g_biasf[cgp * 4], b1 = g_biasf[cgp * 4 + 1];
    float b2 = g_biasf[cgp * 4 + 2], b3 = g_biasf[cgp * 4 + 3];
#pragma unroll
    for (int m = 0; m < 4; m++) {
        int item = base + 4 * ig + m;
        if (item < total) {
            float2 x0 = up2(acc[m][0]), x1 = up2(acc[m][1]);
            *(float4*)(g_cc + (size_t)item * DF + cgp * 4) =
                make_float4(x0.x + b0, x0.y + b1, x1.x + b2, x1.y + b3);
        }
    }
}

// ================= main kernel: direct-LDG fragments, B-only smem =================
#define SMB_HI 0
#define SMB_LO 9216

__global__ __launch_bounds__(128, 3) void fine_main_kernel(
    const float* __restrict__ f0, const float* __restrict__ f1,
    const int* __restrict__ b_ids, const int* __restrict__ cy,
    const int* __restrict__ cx,
    float* __restrict__ out, int N)
{
    __shared__ __align__(16) char smem[DF * BST * 2 * 2];   // 18432
    const u32 sb = smem_u32(smem);
    const int tid = threadIdx.x;
    const int wid = tid >> 5;
    const int lane = tid & 31;
    const int total = 2 * N;
    const int nGroups = (total + 3) >> 2;

    // ---- stage B (once per block) ----
    {
        const char* srcH = (const char*)g_Bhi;
        const char* srcL = (const char*)g_Blo;
        for (int i = tid * 16; i < DF * BST * 2; i += 128 * 16) {
            CP16(sb + SMB_HI + i, srcH + i);
            CP16(sb + SMB_LO + i, srcL + i);
        }
    }
    CP_COMMIT();
    CP_WAIT0();
    __syncthreads();

    const int g = lane >> 2;            // row phase 0..7
    const int c2 = (lane & 3) * 2;      // ch pair base
    const int jc = (lane & 3) * 2;

    // window offsets for the 4 pos this lane touches (clamped, deterministic)
    int woffp[4];
#pragma unroll
    for (int pi = 0; pi < 4; pi++) {
        int p = g + 8 * pi;
        if (p >= WW) p -= 8;
        int dy = p / 5;
        woffp[pi] = dy * WF + (p - dy * 5);
    }

    const u32 bRow = (u32)((((lane >> 4) & 1) * 8 + (lane & 7)) * (BST * 2));
    const u32 bCol = (u32)(((lane >> 3) & 1) * 16);

    for (int group = blockIdx.x; group < nGroups; group += gridDim.x) {
        int item = group * 4 + wid;
        int itemc = item < total ? item : total - 1;
        int s = itemc >= N;
        int p = itemc - s * N;
        const float* fsrc = s ? f1 : f0;
        int b = __ldg(b_ids + p), y = __ldg(cy + p), x = __ldg(cx + p);
        const float* fbase = fsrc + (size_t)b * (DF * HW) + (size_t)(y - 2) * WF + (x - 2);

        const float* bp[4];
#pragma unroll
        for (int pi = 0; pi < 4; pi++) bp[pi] = fbase + woffp[pi];

        // ---- batched gather: 64 LDG.32 into regs (MLP ~64) ----
        float va[64];
#pragma unroll
        for (int kt = 0; kt < 4; kt++)
#pragma unroll
            for (int pi = 0; pi < 4; pi++)
#pragma unroll
                for (int jh = 0; jh < 2; jh++)
#pragma unroll
                    for (int e = 0; e < 2; e++) {
                        int ch = kt * 16 + c2 + jh * 8 + e;
                        va[kt * 16 + pi * 4 + jh * 2 + e] =
                            __ldg(bp[pi] + (size_t)ch * HW);
                    }

        // ---- in-register bf16 hi/lo fragment build ----
        u32 ah[4][2][4], al[4][2][4];   // [kt][mt][j]
#pragma unroll
        for (int kt = 0; kt < 4; kt++)
#pragma unroll
            for (int mt = 0; mt < 2; mt++)
#pragma unroll
                for (int j = 0; j < 4; j++) {
                    int pi = mt * 2 + (j & 1), jh = j >> 1;
                    float v0 = va[kt * 16 + pi * 4 + jh * 2 + 0];
                    float v1 = va[kt * 16 + pi * 4 + jh * 2 + 1];
                    u32 h = packbf(v1, v0);
                    float h0 = __uint_as_float(h << 16);
                    float h1 = __uint_as_float(h & 0xffff0000u);
                    ah[kt][mt][j] = h;
                    al[kt][mt][j] = packbf(v1 - h1, v0 - h0);
                }

        float* ob = out + (size_t)item * (WW * DF) + jc;
        const float* ccb = g_cc + (size_t)itemc * DF + jc;

        // ---- two N-half passes: acc only 32 regs live ----
#pragma unroll
        for (int nh = 0; nh < 2; nh++) {
            float acc[2][4][4];
#pragma unroll
            for (int mt = 0; mt < 2; mt++)
#pragma unroll
                for (int nt = 0; nt < 4; nt++)
#pragma unroll
                    for (int q = 0; q < 4; q++) acc[mt][nt][q] = 0.f;

#pragma unroll
            for (int kt = 0; kt < 4; kt++) {
                u32 bh[2][4], bl[2][4];
#pragma unroll
                for (int ntp = 0; ntp < 2; ntp++) {
                    u32 rowBase = (u32)((nh * 2 + ntp) * 16 * (BST * 2));
                    u32 baddr = rowBase + bRow + (u32)(kt * 32) + bCol;
                    ldsm_x4(bh[ntp], sb + SMB_HI + baddr);
                    ldsm_x4(bl[ntp], sb + SMB_LO + baddr);
                }
#pragma unroll
                for (int ntp = 0; ntp < 2; ntp++)
#pragma unroll
                    for (int sub = 0; sub < 2; sub++) {
                        int nt = ntp * 2 + sub;
                        u32 bhp[2] = {bh[ntp][sub * 2], bh[ntp][sub * 2 + 1]};
                        u32 blp[2] = {bl[ntp][sub * 2], bl[ntp][sub * 2 + 1]};
#pragma unroll
                        for (int mt = 0; mt < 2; mt++) {
                            mma_bf16(acc[mt][nt], ah[kt][mt], bhp);
                            mma_bf16(acc[mt][nt], ah[kt][mt], blp);
                            mma_bf16(acc[mt][nt], al[kt][mt], bhp);
                        }
                    }
            }

            // ---- epilogue for this N-half ----
            if (item < total) {
#pragma unroll
                for (int nt = 0; nt < 4; nt++) {
                    int ntg = nh * 4 + nt;
                    float2 cc = *(const float2*)(ccb + ntg * 8);
#pragma unroll
                    for (int mt = 0; mt < 2; mt++) {
                        int r0 = mt * 16 + g;
                        *(float2*)(ob + r0 * DF + ntg * 8) =
                            make_float2(acc[mt][nt][0] + cc.x, acc[mt][nt][1] + cc.y);
                        if (mt == 0 || g == 0) {
                            int r1 = r0 + 8;
                            *(float2*)(ob + r1 * DF + ntg * 8) =
                                make_float2(acc[mt][nt][2] + cc.x, acc[mt][nt][3] + cc.y);
                        }
                    }
                }
            }
        }
    }
}

extern "C" void kernel_launch(void* const* d_in, const int* in_sizes, int n_in,
                              void* d_out, int out_size) {
    const float* f0    = (const float*)d_in[0];
    const float* f1    = (const float*)d_in[1];
    const float* c0    = (const float*)d_in[2];
    const float* c1    = (const float*)d_in[3];
    const float* Wd    = (const float*)d_in[4];
    const float* bd    = (const float*)d_in[5];
    const float* Wm    = (const float*)d_in[6];
    const float* bm    = (const float*)d_in[7];
    const int*   b_ids = (const int*)d_in[8];
    const int*   cy    = (const int*)d_in[9];
    const int*   cx    = (const int*)d_in[10];
    const int*   ci    = (const int*)d_in[11];
    float* out = (float*)d_out;

    int N = in_sizes[8];
    int total = 2 * N;

    fuse_weights_kernel<<<DC, DF>>>(Wd, Wm, bd, bm);
    prep_B_kernel<<<DF, DF>>>(Wm);

    static int attr_set = 0;
    if (!attr_set) {
        cudaFuncSetAttribute(coarse_kernel,
                             cudaFuncAttributeMaxDynamicSharedMemorySize, CO_SMEM);
        attr_set = 1;
    }

    int cblocks = (total + CO_ITEMS - 1) / CO_ITEMS;
    coarse_kernel<<<cblocks, 256, CO_SMEM>>>(c0, c1, b_ids, ci, N);

    int nGroups = (total + 3) / 4;
    int mblocks = 3 * 152;
    if (mblocks > nGroups) mblocks = nGroups;
    fine_main_kernel<<<mblocks, 128>>>(f0, f1, b_ids, cy, cx, out, N);
}